// round 17
// baseline (speedup 1.0000x reference)
#include <cuda_runtime.h>
#include <cuda_fp16.h>
#include <cstdint>

// ====================== tile/pipeline constants ======================
// Full CTA: 128 threads (4 warps 2x2), tile 128 couts x 112 pixels (2 output rows)
// Half CTA (tail only): tile 64 couts x 112 pixels
// Superstage = 64 ci: A 16384 B (128 rows x 128B) + B 14336 B (112 rows x 128B)
#define STG      30720
#define STAGES   2
#define SMEM_DYN (STAGES * STG + 128)

#define FULL_TILES 1776          // 4 * 444: perfectly divisible wave load
#define GRID_MAIN  1808          // 1776 full + 32 half CTAs (last 16 tiles split in M)

// ====================== device scratch ======================
__device__ __align__(16) __half g_x[(size_t)32 * 58 * 58 * 256];  // padded NHWC fp16
__device__ __align__(16) __half g_w[(size_t)9 * 256 * 256];       // [tap][co][ci] = +-1

// ====================== helpers ======================
__device__ __forceinline__ uint32_t smem_u32(const void* p) {
    uint32_t a;
    asm("{ .reg .u64 t; cvta.to.shared.u64 t, %1; cvt.u32.u64 %0, t; }" : "=r"(a) : "l"(p));
    return a;
}
__device__ __forceinline__ void cp16(uint32_t d, const void* s) {
    asm volatile("cp.async.cg.shared.global [%0], [%1], 16;" :: "r"(d), "l"(s) : "memory");
}
__device__ __forceinline__ void ldsm_x4(uint32_t* r, uint32_t a) {
    asm volatile("ldmatrix.sync.aligned.m8n8.x4.shared.b16 {%0,%1,%2,%3}, [%4];"
                 : "=r"(r[0]), "=r"(r[1]), "=r"(r[2]), "=r"(r[3]) : "r"(a));
}
__device__ __forceinline__ void ldsm_x2(uint32_t* r, uint32_t a) {
    asm volatile("ldmatrix.sync.aligned.m8n8.x2.shared.b16 {%0,%1}, [%2];"
                 : "=r"(r[0]), "=r"(r[1]) : "r"(a));
}
__device__ __forceinline__ void mma16816(float* c, uint32_t a0, uint32_t a1, uint32_t a2,
                                         uint32_t a3, uint32_t b0, uint32_t b1) {
    asm volatile(
        "mma.sync.aligned.m16n8k16.row.col.f32.f16.f16.f32 "
        "{%0,%1,%2,%3}, {%4,%5,%6,%7}, {%8,%9}, {%0,%1,%2,%3};"
        : "+f"(c[0]), "+f"(c[1]), "+f"(c[2]), "+f"(c[3])
        : "r"(a0), "r"(a1), "r"(a2), "r"(a3), "r"(b0), "r"(b1));
}

// ====================== fused prep kernel ======================
// blocks [0,3584): x transpose NCHW f32 -> padded NHWC fp16
// blocks [3584,3616): pad-border zeroing (one block per image)
// blocks [3616,4192): weight binarize, 4 elems/thread via float4
__global__ void prep_all_kernel(const float* __restrict__ x, const float* __restrict__ w) {
    const int b = blockIdx.x;
    if (b < 3584) {
        __shared__ float tile[128][57];
        const int ch = b & 1;
        const int h  = (b >> 1) % 56;
        const int n  = (b >> 1) / 56;
        const float* src = x + (size_t)(n * 256 + ch * 128) * 3136 + h * 56;
        for (int i = threadIdx.x; i < 128 * 56; i += 256) {
            int ci = i / 56, ww = i - 56 * ci;
            tile[ci][ww] = src[(size_t)ci * 3136 + ww];
        }
        __syncthreads();
        __half* dst = g_x + (size_t)n * 861184 + ((h + 1) * 58 + 1) * 256;
        for (int j = threadIdx.x; j < 64 * 56; j += 256) {
            int ww = j >> 6, cp = j & 63;
            int ci = ch * 128 + 2 * cp;
            __half2 v = __floats2half2_rn(tile[2 * cp][ww], tile[2 * cp + 1][ww]);
            *reinterpret_cast<__half2*>(dst + (size_t)ww * 256 + ci) = v;
        }
    } else if (b < 3616) {
        const int n = b - 3584;
        __half* xb = g_x + (size_t)n * 861184;
        for (int c = threadIdx.x; c < 7296; c += 256) { // 228 border px * 32 uint4
            int px = c >> 5, q = c & 31;
            int h, ww;
            if (px < 58)       { h = 0;        ww = px; }
            else if (px < 116) { h = 57;       ww = px - 58; }
            else if (px < 172) { h = px - 115; ww = 0; }
            else               { h = px - 171; ww = 57; }
            reinterpret_cast<uint4*>(xb + ((size_t)h * 58 + ww) * 256)[q] =
                make_uint4(0u, 0u, 0u, 0u);
        }
    } else {
        int i0 = (b - 3616) * 1024 + threadIdx.x * 4;
        float4 v = *reinterpret_cast<const float4*>(w + i0);
        float vv[4] = {v.x, v.y, v.z, v.w};
#pragma unroll
        for (int e = 0; e < 4; e++) {
            int idx = i0 + e;
            int co  = idx / 2304;
            int r   = idx - co * 2304;
            int ci  = r / 9;
            int tap = r - ci * 9;
            g_w[(size_t)(tap * 256 + co) * 256 + ci] = __float2half(vv[e] >= 0.f ? 1.f : -1.f);
        }
    }
}

// ====================== tile compute (templated on warp M-frags) ======================
// MI=4: CTA M=128 (warp tile 64x56). MI=2: CTA M=64 (warp tile 32x56). B path identical.
template <int MI>
__device__ __forceinline__ void conv_tile(
    const __half* __restrict__ xn, int coBase, int h0, uint32_t base,
    int tid, int lane, int wm, int wn, int n,
    const float* __restrict__ bias, float* __restrict__ out)
{
    const int g = lane >> 2;
    const int t = lane & 3;

    // ---- cp.async affine bases (16B chunks; row&7 invariant across i since step=16) ----
    const int r0  = tid >> 3;
    const int cbk = tid & 7;
    const uint32_t cb8 = (uint32_t)(cbk * 8);
    const uint32_t swz = (uint32_t)((cbk ^ (r0 & 7)) << 4);
    const uint32_t aD0 = (uint32_t)(r0 * 128) + swz;
    const uint32_t bD0 = 16384u + aD0;
    const uint32_t aG0 = (uint32_t)((coBase + r0) * 256) + cb8;

    auto load_ss = [&](int ss, uint32_t sb) {
        int tap = ss >> 2, kc2 = ss & 3;
        int dh  = tap / 3, dw = tap - 3 * dh;
        const __half* wp = g_w + tap * 65536 + kc2 * 64 + aG0;
#pragma unroll
        for (int i = 0; i < MI * 2; i++)              // A rows: MI*32
            cp16(sb + aD0 + (uint32_t)(i * 2048), wp + i * 4096);
        uint32_t bgc = (uint32_t)((((h0 + dh) * 58 + dw) * 256) + kc2 * 64) + cb8;
#pragma unroll
        for (int i = 0; i < 7; i++) {                 // B: 112 pixel rows
            int prow = r0 + 16 * i;
            uint32_t off = bgc + (uint32_t)(prow * 256) + (prow >= 56 ? 512u : 0u);
            cp16(sb + bD0 + (uint32_t)(i * 2048), xn + off);
        }
        asm volatile("cp.async.commit_group;" ::: "memory");
    };

    // ---- ldmatrix lane addresses (kstep 0; kstep k = XOR k<<5) ----
    uint32_t rA[MI];
    {
        int rl   = (lane & 7) + ((lane >> 3) & 1) * 8;
        int half = lane >> 4;
#pragma unroll
        for (int mi = 0; mi < MI; mi++) {
            int row = wm * (MI * 16) + mi * 16 + rl;
            rA[mi] = (uint32_t)(row * 128 + ((half ^ (row & 7)) << 4));
        }
    }
    uint32_t rB[4];
    {
        int pl   = (lane & 7) + (lane >> 4) * 8;
        int half = (lane >> 3) & 1;
#pragma unroll
        for (int pi = 0; pi < 3; pi++) {
            int pix = wn * 56 + pi * 16 + pl;
            rB[pi] = 16384u + (uint32_t)(pix * 128 + ((half ^ (pix & 7)) << 4));
        }
        int pix6 = wn * 56 + 48 + (lane & 7);
        rB[3] = 16384u + (uint32_t)(pix6 * 128 + ((half ^ (pix6 & 7)) << 4));
    }

    float acc[MI][7][4];
#pragma unroll
    for (int mi = 0; mi < MI; mi++)
#pragma unroll
        for (int ni = 0; ni < 7; ni++)
#pragma unroll
            for (int k = 0; k < 4; k++) acc[mi][ni][k] = 0.f;

    // ---- prologue: superstage 0 ----
    load_ss(0, base);
    asm volatile("cp.async.wait_group 0;" ::: "memory");
    __syncthreads();

    // ---- mainloop: 36 superstages, 2 buffers ----
    for (int ss = 0; ss < 36; ss++) {
        if (ss < 35) load_ss(ss + 1, base + (uint32_t)(((ss + 1) & 1) * STG));

        const uint32_t sb = base + (uint32_t)((ss & 1) * STG);
#pragma unroll
        for (int k = 0; k < 4; k++) {
            const uint32_t xr = (uint32_t)(k << 5);
            uint32_t a[MI][4];
#pragma unroll
            for (int mi = 0; mi < MI; mi++) ldsm_x4(a[mi], sb + (rA[mi] ^ xr));
#pragma unroll
            for (int pi = 0; pi < 3; pi++) {
                uint32_t bfr[4];
                ldsm_x4(bfr, sb + (rB[pi] ^ xr));
#pragma unroll
                for (int mi = 0; mi < MI; mi++) {
                    mma16816(acc[mi][2 * pi],     a[mi][0], a[mi][1], a[mi][2], a[mi][3], bfr[0], bfr[1]);
                    mma16816(acc[mi][2 * pi + 1], a[mi][0], a[mi][1], a[mi][2], a[mi][3], bfr[2], bfr[3]);
                }
            }
            uint32_t b6[2];
            ldsm_x2(b6, sb + (rB[3] ^ xr));
#pragma unroll
            for (int mi = 0; mi < MI; mi++)
                mma16816(acc[mi][6], a[mi][0], a[mi][1], a[mi][2], a[mi][3], b6[0], b6[1]);
        }
        asm volatile("cp.async.wait_group 0;" ::: "memory");
        __syncthreads();
    }

    // ---- epilogue: registers -> gmem (float2), + binarized bias ----
    const int h = h0 + wn;
#pragma unroll
    for (int mi = 0; mi < MI; mi++) {
        int mlo = coBase + wm * (MI * 16) + mi * 16 + g;
        float blo = (bias[mlo]     >= 0.f) ? 1.f : -1.f;
        float bhi = (bias[mlo + 8] >= 0.f) ? 1.f : -1.f;
        size_t olo = ((size_t)(n * 256 + mlo)) * 3136 + h * 56;
        size_t ohi = olo + (size_t)8 * 3136;
#pragma unroll
        for (int ni = 0; ni < 7; ni++) {
            int ww = ni * 8 + 2 * t;
            float2 v0 = make_float2(acc[mi][ni][0] + blo, acc[mi][ni][1] + blo);
            float2 v1 = make_float2(acc[mi][ni][2] + bhi, acc[mi][ni][3] + bhi);
            *reinterpret_cast<float2*>(out + olo + ww) = v0;
            *reinterpret_cast<float2*>(out + ohi + ww) = v1;
        }
    }
}

// ====================== main kernel ======================
// grid 1808: bids [0,1776) = full tiles (M=128); bids [1776,1808) = half CTAs
// (M=64) covering tiles 1776..1791 — launched last so work-stealing drops them
// into the ragged end of the wave.
__global__ void __launch_bounds__(128, 3)
bconv_main_kernel(const float* __restrict__ bias, float* __restrict__ out) {
    extern __shared__ char dsm[];
    const uint32_t base = (smem_u32(dsm) + 127u) & ~127u;

    const int tid  = threadIdx.x;
    const int lane = tid & 31;
    const int wid  = tid >> 5;
    const int wm   = wid >> 1;
    const int wn   = wid & 1;

    const int bid = blockIdx.x;
    int tile, coBase;
    if (bid < FULL_TILES) {
        tile   = bid;
        coBase = (tile & 1) * 128;
    } else {
        int hid = bid - FULL_TILES;            // 0..31
        tile    = FULL_TILES + (hid >> 1);
        coBase  = (tile & 1) * 128 + (hid & 1) * 64;
    }
    const int rp = (tile >> 1) % 28;
    const int n  = tile / 56;
    const int h0 = rp * 2;
    const __half* xn = g_x + (size_t)n * 861184;

    if (bid < FULL_TILES)
        conv_tile<4>(xn, coBase, h0, base, tid, lane, wm, wn, n, bias, out);
    else
        conv_tile<2>(xn, coBase, h0, base, tid, lane, wm, wn, n, bias, out);
}

// ====================== launch ======================
extern "C" void kernel_launch(void* const* d_in, const int* in_sizes, int n_in,
                              void* d_out, int out_size) {
    const float* x    = (const float*)d_in[0];
    const float* w    = (const float*)d_in[1];
    const float* bias = (const float*)d_in[2];
    float* out        = (float*)d_out;

    cudaFuncSetAttribute(bconv_main_kernel,
                         cudaFuncAttributeMaxDynamicSharedMemorySize, SMEM_DYN);

    prep_all_kernel<<<4192, 256>>>(x, w);
    bconv_main_kernel<<<GRID_MAIN, 128, SMEM_DYN>>>(bias, out);
}